// round 12
// baseline (speedup 1.0000x reference)
#include <cuda_runtime.h>
#include <cuda_fp16.h>

#define TOKENS 32768
#define DMODEL 2048
#define NEXP   64
#define TBLK   128
#define KC     32
#define NCHUNK (DMODEL / KC)   // 64
#define NTH    256
#define XP     40              // smem pitch in fp16 elems (80B)
#define LG_LD  68
#define TAU    8e-3f

// stage byte offsets (hi tiles only)
#define XH_OFF 0               // 128*40*2 = 10240
#define WH_OFF 10240           // 64*40*2  = 5120
#define STAGE  15360
#define SMEM_DYN 35328         // max(2*STAGE, logits 34816 + pad)

typedef unsigned int u32;
typedef unsigned long long u64;

__device__ int g_cnt;
__device__ int g_list[TOKENS];

static __device__ __forceinline__ u32 smem_u32(const void* p) {
    u32 a;
    asm("{ .reg .u64 t; cvta.to.shared.u64 t, %1; cvt.u32.u64 %0, t; }" : "=r"(a) : "l"(p));
    return a;
}

static __device__ __forceinline__ u64 h4(float4 v) {
    __half2 a = __float22half2_rn(make_float2(v.x, v.y));
    __half2 b = __float22half2_rn(make_float2(v.z, v.w));
    u32 ua = *reinterpret_cast<u32*>(&a);
    u32 ub = *reinterpret_cast<u32*>(&b);
    return (u64)ua | ((u64)ub << 32);
}

#define LDSM_X4(R, addr)                                                      \
    asm volatile("ldmatrix.sync.aligned.m8n8.x4.shared.b16 {%0,%1,%2,%3}, [%4];" \
        : "=r"((R)[0]), "=r"((R)[1]), "=r"((R)[2]), "=r"((R)[3]) : "r"(addr))

#define MMA_F16(C, A, B0, B1)                                                 \
    asm volatile("mma.sync.aligned.m16n8k16.row.col.f32.f16.f16.f32 "         \
        "{%0,%1,%2,%3}, {%4,%5,%6,%7}, {%8,%9}, {%0,%1,%2,%3};"               \
        : "+f"((C)[0]), "+f"((C)[1]), "+f"((C)[2]), "+f"((C)[3])              \
        : "r"((A)[0]), "r"((A)[1]), "r"((A)[2]), "r"((A)[3]), "r"(B0), "r"(B1))

__global__ void reset_kernel() { g_cnt = 0; }

__global__ __launch_bounds__(NTH, 2)
void gemm16_kernel(const float* __restrict__ x,
                   const float* __restrict__ w,
                   float* __restrict__ out)
{
    extern __shared__ char dsm[];
    __shared__ float inv_s[TBLK];

    const int tid = threadIdx.x;
    const int wid = tid >> 5;
    const int lid = tid & 31;
    const int t0  = blockIdx.x * TBLK;
    const u32 dsm_b = smem_u32(dsm);

    // global load geometry (round-5 proven)
    const int gr = tid >> 3;            // 0..31
    const int gc = tid & 7;
    const float* xbase = x + (size_t)(t0 + gr) * DMODEL + gc * 4;
    const float* wbase = w + (size_t)gr * DMODEL + gc * 4;
    const u32 sts_off = (u32)((gr * XP + gc * 4) * 2);

    // warp tile: 32 tokens x 32 experts
    const int wtok0 = (wid >> 1) * 32;
    const int wexp0 = (wid & 1) * 32;
    const int arow = (lid & 7) + ((lid >> 3) & 1) * 8;
    const int acol = ((lid >> 4) & 1) * 8;
    const int brow = (lid & 7) + ((lid >> 4) & 1) * 8;
    const int bcol = ((lid >> 3) & 1) * 8;
    const u32 a_off = (u32)(((wtok0 + arow) * XP + acol) * 2);
    const u32 b_off = (u32)(((wexp0 + brow) * XP + bcol) * 2);

    float acc[2][4][4];
    #pragma unroll
    for (int mt = 0; mt < 2; mt++)
        #pragma unroll
        for (int nt = 0; nt < 4; nt++)
            #pragma unroll
            for (int c = 0; c < 4; c++)
                acc[mt][nt][c] = 0.0f;

    float4 xr[4], wr[2];

    // prologue: chunk 0 -> stage 0; prefetch chunk 1
    #pragma unroll
    for (int i = 0; i < 4; i++) xr[i] = *(const float4*)(xbase + (size_t)i * 32 * DMODEL);
    #pragma unroll
    for (int i = 0; i < 2; i++) wr[i] = *(const float4*)(wbase + (size_t)i * 32 * DMODEL);
    {
        char* st = dsm;
        #pragma unroll
        for (int i = 0; i < 4; i++)
            *(u64*)(st + XH_OFF + sts_off + i * 32 * XP * 2) = h4(xr[i]);
        #pragma unroll
        for (int i = 0; i < 2; i++)
            *(u64*)(st + WH_OFF + sts_off + i * 32 * XP * 2) = h4(wr[i]);
    }
    #pragma unroll
    for (int i = 0; i < 4; i++) xr[i] = *(const float4*)(xbase + KC + (size_t)i * 32 * DMODEL);
    #pragma unroll
    for (int i = 0; i < 2; i++) wr[i] = *(const float4*)(wbase + KC + (size_t)i * 32 * DMODEL);

    for (int ch = 0; ch < NCHUNK; ++ch) {
        __syncthreads();

        // STS next stage from prefetched regs
        if (ch + 1 < NCHUNK) {
            char* st = dsm + ((ch + 1) & 1) * STAGE;
            #pragma unroll
            for (int i = 0; i < 4; i++)
                *(u64*)(st + XH_OFF + sts_off + i * 32 * XP * 2) = h4(xr[i]);
            #pragma unroll
            for (int i = 0; i < 2; i++)
                *(u64*)(st + WH_OFF + sts_off + i * 32 * XP * 2) = h4(wr[i]);
        }
        if (ch + 2 < NCHUNK) {
            const int k0 = (ch + 2) * KC;
            #pragma unroll
            for (int i = 0; i < 4; i++)
                xr[i] = *(const float4*)(xbase + k0 + (size_t)i * 32 * DMODEL);
            #pragma unroll
            for (int i = 0; i < 2; i++)
                wr[i] = *(const float4*)(wbase + k0 + (size_t)i * 32 * DMODEL);
        }

        const u32 sb = dsm_b + (ch & 1) * STAGE;
        const u32 ah_b = sb + XH_OFF + a_off;
        const u32 bh_b = sb + WH_OFF + b_off;

        #pragma unroll
        for (int ks = 0; ks < KC / 16; ks++) {
            const u32 ko = ks * 32;
            u32 ah[8], bh[8];
            #pragma unroll
            for (int mt = 0; mt < 2; mt++)
                LDSM_X4(ah + mt * 4, ah_b + mt * (16 * XP * 2) + ko);
            #pragma unroll
            for (int ng = 0; ng < 2; ng++)
                LDSM_X4(bh + ng * 4, bh_b + ng * (16 * XP * 2) + ko);

            #pragma unroll
            for (int mt = 0; mt < 2; mt++)
                #pragma unroll
                for (int nt = 0; nt < 4; nt++)
                    MMA_F16(acc[mt][nt], ah + mt * 4, bh[nt * 2], bh[nt * 2 + 1]);
        }
    }

    // epilogue: accs -> smem logits
    __syncthreads();
    float* logits = (float*)dsm;
    {
        const int crow = lid >> 2;
        const int ccol = (lid & 3) * 2;
        #pragma unroll
        for (int mt = 0; mt < 2; mt++)
            #pragma unroll
            for (int nt = 0; nt < 4; nt++) {
                int tok = wtok0 + mt * 16 + crow;
                int ex  = wexp0 + nt * 8 + ccol;
                *(float2*)&logits[tok * LG_LD + ex] =
                    make_float2(acc[mt][nt][0], acc[mt][nt][1]);
                *(float2*)&logits[(tok + 8) * LG_LD + ex] =
                    make_float2(acc[mt][nt][2], acc[mt][nt][3]);
            }
    }
    __syncthreads();

    if (tid < TBLK) {
        const int t = tid;
        float* row = &logits[t * LG_LD];

        // top-3 (m3 needed for flip-safety margin on i2)
        float m1 = -3.4e38f, m2 = -3.4e38f, m3 = -3.4e38f;
        int   i1 = 0,        i2 = 0;
        #pragma unroll
        for (int e = 0; e < NEXP; e++) {
            float v = row[e];
            if (v > m1)      { m3 = m2; m2 = m1; i2 = i1; m1 = v; i1 = e; }
            else if (v > m2) { m3 = m2; m2 = v; i2 = e; }
            else if (v > m3) { m3 = v; }
        }

        int gt = t0 + t;
        if ((m1 - m2 < TAU) || (m2 - m3 < TAU)) {
            int s = atomicAdd(&g_cnt, 1);
            g_list[s] = gt;
        }

        float s = 0.0f;
        #pragma unroll
        for (int e = 0; e < NEXP; e++) {
            float ev = __expf(row[e] - m1);
            row[e] = ev;
            s += ev;
        }
        inv_s[t] = 1.0f / s;

        float e2v = __expf(m2 - m1);
        float g1  = 1.0f / (1.0f + e2v);

        out[2 * gt + 0] = g1;
        out[2 * gt + 1] = e2v * g1;
        float* oidx = out + (size_t)2 * TOKENS;
        oidx[2 * gt + 0] = (float)i1;
        oidx[2 * gt + 1] = (float)i2;
    }
    __syncthreads();

    float* oprob = out + (size_t)4 * TOKENS;
    for (int f = tid; f < TBLK * (NEXP / 4); f += NTH) {
        int r = f >> 4, c4 = f & 15;
        float4 ev = *(const float4*)&logits[r * LG_LD + c4 * 4];
        float inv = inv_s[r];
        float4 p = make_float4(ev.x * inv, ev.y * inv, ev.z * inv, ev.w * inv);
        *(float4*)&oprob[(size_t)(t0 + r) * NEXP + c4 * 4] = p;
    }
}

// exact fp32 recompute for flagged tokens; overwrites gates/idx/probs
__global__ __launch_bounds__(256)
void recheck_kernel(const float* __restrict__ x,
                    const float* __restrict__ w,
                    float* __restrict__ out)
{
    __shared__ float xs[8][128];
    __shared__ float ws[64][129];   // +1 pad
    __shared__ float lg[8][NEXP];
    __shared__ int   toks[8];

    const int tid = threadIdx.x;
    const int n = g_cnt;

    for (int base = blockIdx.x * 8; base < n; base += gridDim.x * 8) {
        const int cnt = min(8, n - base);
        if (tid < 8) toks[tid] = g_list[base + min(tid, cnt - 1)];
        __syncthreads();

        const int e = tid & 63;
        const int g = tid >> 6;      // 0..3; handles tokens g and g+4
        float a0 = 0.0f, a1 = 0.0f;

        for (int kc = 0; kc < 16; kc++) {
            for (int i = tid; i < 8 * 128; i += 256) {
                int tt = i >> 7, kk = i & 127;
                xs[tt][kk] = x[(size_t)toks[tt] * DMODEL + kc * 128 + kk];
            }
            for (int i = tid; i < 64 * 128; i += 256) {
                int ee = i >> 7, kk = i & 127;
                ws[ee][kk] = w[(size_t)ee * DMODEL + kc * 128 + kk];
            }
            __syncthreads();
            #pragma unroll 8
            for (int kk = 0; kk < 128; kk++) {
                float wv = ws[e][kk];
                a0 = fmaf(xs[g][kk], wv, a0);
                a1 = fmaf(xs[g + 4][kk], wv, a1);
            }
            __syncthreads();
        }
        lg[g][e] = a0;
        lg[g + 4][e] = a1;
        __syncthreads();

        if (tid < cnt) {
            const int gt = toks[tid];
            float* row = lg[tid];

            float m1 = -3.4e38f, m2 = -3.4e38f;
            int   i1 = 0,        i2 = 0;
            #pragma unroll
            for (int ee = 0; ee < NEXP; ee++) {
                float v = row[ee];
                if (v > m1)      { m2 = m1; i2 = i1; m1 = v; i1 = ee; }
                else if (v > m2) { m2 = v; i2 = ee; }
            }
            float s = 0.0f;
            float ev[NEXP];
            #pragma unroll
            for (int ee = 0; ee < NEXP; ee++) {
                ev[ee] = __expf(row[ee] - m1);
                s += ev[ee];
            }
            float inv = 1.0f / s;
            float e2v = __expf(m2 - m1);
            float g1  = 1.0f / (1.0f + e2v);

            out[2 * gt + 0] = g1;
            out[2 * gt + 1] = e2v * g1;
            float* oidx = out + (size_t)2 * TOKENS;
            oidx[2 * gt + 0] = (float)i1;
            oidx[2 * gt + 1] = (float)i2;
            float* op = out + (size_t)4 * TOKENS + (size_t)gt * NEXP;
            for (int ee = 0; ee < NEXP; ee++) op[ee] = ev[ee] * inv;
        }
        __syncthreads();
    }
}

extern "C" void kernel_launch(void* const* d_in, const int* in_sizes, int n_in,
                              void* d_out, int out_size) {
    const float* x = (const float*)d_in[0];
    const float* w = (const float*)d_in[1];
    float* out = (float*)d_out;
    reset_kernel<<<1, 1>>>();
    cudaFuncSetAttribute(gemm16_kernel,
                         cudaFuncAttributeMaxDynamicSharedMemorySize, SMEM_DYN);
    gemm16_kernel<<<TOKENS / TBLK, NTH, SMEM_DYN>>>(x, w, out);
    recheck_kernel<<<256, 256>>>(x, w, out);
}